// round 17
// baseline (speedup 1.0000x reference)
#include <cuda_runtime.h>

// GaussianBlur v9 = v6 tile & phase-2 (proven 50.9us kernel) with phase 1
// switched to f32x2 column-pair scatter (halves phase-1 FMA issue slots).
// depthwise 21x21 Gaussian (sigma=5), reflect pad 10, [32,3,512,512] fp32.
// Tile 128x64 outputs, 256 threads, 5 CTA/SM:
//   phase 1: VERTICAL 21-tap, 2 adjacent cols/thread: LDG.64 + fma.rn.f32x2
//            (weights folded to 64-bit immediates). Scatter into 16 u64
//            accumulators, QROWS=16 (2.25x y-halo, same as v6), refills
//            front-batched 6-wide. 296 pair-tasks. Dense LDG.64/STS.64.
//   phase 2: HORIZONTAL 21-tap from smem, v3/v6 verbatim: 6x LDS.128
//            conflict-free 4-output windows, FFMA-imm, STG.128 dense.

#define W_ 512
#define H_ 512
#define NIMG 96
#define PAD 10

#define TX 128
#define TY 64
#define VCOLS   148                 // TX + 2*PAD
#define VSTRIDE 148                 // floats per smem row (592B)
#define QROWS   16                  // v-pass outputs per pair-task
#define VWIN    (QROWS + 2 * PAD)   // 36 rows read per task
#define NPAIR   (VCOLS / 2)         // 74 column pairs
#define NTASK1  (NPAIR * (TY / QROWS))   // 296

typedef unsigned long long u64;

// ---- weights: exp(-(d^2)/50)/12.089199128 (validated rel_err 3.4e-7) ------
#define KWD0  0.01119473
#define KWD1  0.01636989
#define KWD2  0.02299883
#define KWD3  0.03104516
#define KWD4  0.04026340
#define KWD5  0.05017128
#define KWD6  0.06006594
#define KWD7  0.06909227
#define KWD8  0.07635877
#define KWD9  0.08108053
#define KWD10 0.08271847

// constexpr IEEE-754 float encoder (round to nearest; inputs never tie)
__host__ __device__ constexpr unsigned fbits(double x) {
    int e = 0;
    while (x >= 2.0) { x *= 0.5; ++e; }
    while (x < 1.0)  { x *= 2.0; --e; }
    double m = (x - 1.0) * 8388608.0;
    unsigned mi = (unsigned)(m + 0.5);
    unsigned ee = (unsigned)(e + 127);
    if (mi == 8388608u) { mi = 0u; ee += 1u; }
    return (ee << 23) | mi;
}
__host__ __device__ constexpr u64 wpair(double x) {
    u64 b = fbits(x); return (b << 32) | b;
}

#define KW2_INIT const u64 KW2[21] = { \
    wpair(KWD0),  wpair(KWD1),  wpair(KWD2),  wpair(KWD3),  wpair(KWD4), \
    wpair(KWD5),  wpair(KWD6),  wpair(KWD7),  wpair(KWD8),  wpair(KWD9), \
    wpair(KWD10), \
    wpair(KWD9),  wpair(KWD8),  wpair(KWD7),  wpair(KWD6),  wpair(KWD5), \
    wpair(KWD4),  wpair(KWD3),  wpair(KWD2),  wpair(KWD1),  wpair(KWD0) }

#define KW_INIT const float KW[21] = { \
    (float)KWD0,  (float)KWD1,  (float)KWD2,  (float)KWD3,  (float)KWD4, \
    (float)KWD5,  (float)KWD6,  (float)KWD7,  (float)KWD8,  (float)KWD9, \
    (float)KWD10, \
    (float)KWD9,  (float)KWD8,  (float)KWD7,  (float)KWD6,  (float)KWD5, \
    (float)KWD4,  (float)KWD3,  (float)KWD2,  (float)KWD1,  (float)KWD0 }

__device__ __forceinline__ int reflect512(int i) {
    // jnp.pad mode="reflect": -k -> k, 511+k -> 511-k (single reflection)
    i = (i < 0) ? -i : i;
    return (i > 511) ? (1022 - i) : i;
}

__device__ __forceinline__ u64 fma2(u64 a, u64 b, u64 c) {
    u64 d;
    asm("fma.rn.f32x2 %0, %1, %2, %3;" : "=l"(d) : "l"(a), "l"(b), "l"(c));
    return d;
}
__device__ __forceinline__ u64 pack2(float lo, float hi) {
    u64 r;
    asm("mov.b64 %0, {%1, %2};" : "=l"(r) : "f"(lo), "f"(hi));
    return r;
}

// ---- Phase-1 task: vertical conv of one column PAIR, 16 output rows -------
// Scatter form (validated in v5): row j feeds acc[rr] for
// rr in [max(0,j-20), min(15,j)] with weight KW2[j-rr]. Loads front-batched
// per 6-row chunk (36 = 6x6), keeping MLP>=6 without a latency-bound ring.
template <class F>
__device__ __forceinline__ void vpair_body(F fetch, float* __restrict__ dst) {
    KW2_INIT;
    u64 acc[QROWS];
    #pragma unroll
    for (int r = 0; r < QROWS; ++r) acc[r] = 0ull;

    u64 v[6];
    #pragma unroll
    for (int ch = 0; ch < 6; ++ch) {
        const int base = ch * 6;
        #pragma unroll
        for (int j = 0; j < 6; ++j)
            v[j] = fetch(base + j);
        #pragma unroll
        for (int j = 0; j < 6; ++j) {
            const int J = base + j;
            #pragma unroll
            for (int rr = 0; rr < QROWS; ++rr)
                if (rr <= J && J - rr <= 20)
                    acc[rr] = fma2(KW2[J - rr], v[j], acc[rr]);
        }
    }
    #pragma unroll
    for (int rr = 0; rr < QROWS; ++rr)
        *reinterpret_cast<u64*>(dst + rr * VSTRIDE) = acc[rr];
}

// Cold path: x and/or y border pairs (reflected, possibly non-adjacent cols).
__device__ __noinline__ void vpair_border(const float* __restrict__ img,
                                          float* __restrict__ dst,
                                          int yb, int gx) {
    const int rl = reflect512(gx), rh = reflect512(gx + 1);
    vpair_body([&](int j) {
        const size_t ro = (size_t)reflect512(yb + j) * W_;
        return pack2(img[ro + rl], img[ro + rh]);
    }, dst);
}

__global__ __launch_bounds__(256, 5)
void blur_v9(const float* __restrict__ in, float* __restrict__ out) {
    KW_INIT;
    __shared__ __align__(16) float Vs[TY * VSTRIDE];   // 37888 B

    const int n   = blockIdx.z;
    const int x0  = blockIdx.x * TX;
    const int y0  = blockIdx.y * TY;
    const int tid = threadIdx.x;

    const float* __restrict__ img = in + (size_t)n * (H_ * W_);

    // ---- Phase 1: vertical conv, gmem -> Vs (296 pair-tasks) --------------
    #pragma unroll 1
    for (int tau = tid; tau < NTASK1; tau += 256) {
        const int q  = tau / NPAIR;            // 0..3 (y-chunk)
        const int pr = tau - q * NPAIR;        // 0..73 (column pair)
        const int gx = x0 - PAD + 2 * pr;      // even -> LDG.64 aligned
        const int yb = y0 + q * QROWS - PAD;
        float* dst = Vs + (q * QROWS) * VSTRIDE + 2 * pr;

        if (gx >= 0 && gx + 1 < W_ && yb >= 0 && yb + VWIN <= H_) {
            const u64* __restrict__ p =
                reinterpret_cast<const u64*>(img + (size_t)yb * W_ + gx);
            vpair_body([&](int j) { return p[(size_t)j * (W_ / 2)]; }, dst);
        } else {
            vpair_border(img, dst, yb, gx);
        }
    }
    __syncthreads();

    // ---- Phase 2: horizontal conv, Vs -> gmem (v3/v6 verbatim) ------------
    // Warp = one row (stride 8), lane g -> outputs [4g..4g+3] from window
    // Vs[r][4g..4g+23]: 6x LDS.128 at 16B-stride starts (conflict-free
    // phases), FFMA-imm, STG.128 dense. 8 warps x 8 iters = 64 rows exact.
    float* __restrict__ outimg = out + (size_t)n * (H_ * W_);
    const int g  = tid & 31;
    const int r0 = tid >> 5;

    #pragma unroll
    for (int i = 0; i < 8; ++i) {
        const int r = r0 + i * 8;
        const float* __restrict__ src = Vs + r * VSTRIDE + 4 * g;

        float wv[24];
        #pragma unroll
        for (int j = 0; j < 6; ++j) {
            float4 t = *reinterpret_cast<const float4*>(src + 4 * j);
            wv[4 * j + 0] = t.x; wv[4 * j + 1] = t.y;
            wv[4 * j + 2] = t.z; wv[4 * j + 3] = t.w;
        }

        float h0 = 0.f, h1 = 0.f, h2 = 0.f, h3 = 0.f;
        #pragma unroll
        for (int k = 0; k < 21; ++k) {
            const float w = KW[k];
            h0 = fmaf(w, wv[k + 0], h0);
            h1 = fmaf(w, wv[k + 1], h1);
            h2 = fmaf(w, wv[k + 2], h2);
            h3 = fmaf(w, wv[k + 3], h3);
        }
        *reinterpret_cast<float4*>(outimg + (size_t)(y0 + r) * W_ + x0 + 4 * g)
            = make_float4(h0, h1, h2, h3);
    }
}

extern "C" void kernel_launch(void* const* d_in, const int* in_sizes, int n_in,
                              void* d_out, int out_size) {
    const float* x = (const float*)d_in[0];
    float* out = (float*)d_out;
    (void)in_sizes; (void)n_in; (void)out_size;

    // 4 x-tiles, 8 y-tiles, 96 images = 3072 blocks of 256 threads
    blur_v9<<<dim3(W_ / TX, H_ / TY, NIMG), 256>>>(x, out);
}